// round 5
// baseline (speedup 1.0000x reference)
#include <cuda_runtime.h>
#include <stdint.h>
#include <math.h>

#define BATCH 32
#define NBOX  10647          // 507 + 2028 + 8112
#define KTOP  512
#define NBIN  4096
#define T13   (BATCH * 3 * 169)
#define T26   (BATCH * 3 * 676)
#define T52   (BATCH * 3 * 2704)
#define TTOT  (T13 + T26 + T52)

// ---------------- scratch (no allocation allowed) ----------------
__device__ float              g_boxes[BATCH * NBOX * 8];  // x1,y1,x2,y2,conf,cls,pad,pad
__device__ unsigned           g_skey [BATCH * NBOX];      // mono32(score)
__device__ int                g_hist [BATCH * NBIN];
__device__ int                g_cnt  [BATCH];
__device__ unsigned long long g_sel  [BATCH * 1024];

__device__ __forceinline__ float sigm(float x) {
    return 1.0f / (1.0f + expf(-x));
}

// ---------------- zero scratch counters ---------------------------
__global__ void zero_kernel()
{
    int i = blockIdx.x * blockDim.x + threadIdx.x;
    if (i < BATCH * NBIN) g_hist[i] = 0;
    if (i < BATCH)        g_cnt[i]  = 0;
}

// ---------------- fused decode + histogram ------------------------
__global__ void __launch_bounds__(256)
decode_all_kernel(const float* __restrict__ o13, const float* __restrict__ o26,
                  const float* __restrict__ o52, const float* __restrict__ a13,
                  const float* __restrict__ a26, const float* __restrict__ a52)
{
    int gid = blockIdx.x * blockDim.x + threadIdx.x;
    if (gid >= TTOT) return;

    const float* src; const float* anc;
    int HW, W, n_off, r;
    float t;
    if (gid < T13)            { r = gid;             src = o13; anc = a13; HW = 169;  W = 13; n_off = 0;    t = 32.0f; }
    else if (gid < T13 + T26) { r = gid - T13;       src = o26; anc = a26; HW = 676;  W = 26; n_off = 507;  t = 16.0f; }
    else                      { r = gid - T13 - T26; src = o52; anc = a52; HW = 2704; W = 52; n_off = 2535; t = 8.0f;  }

    int b    = r / (3 * HW);
    int q    = r - b * 3 * HW;
    int a    = q / HW;
    int cell = q - a * HW;
    int y    = cell / W;
    int x    = cell - y * W;

    const float* p = src + ((size_t)b * 255 + (size_t)a * 85) * HW + cell;

    float tx = p[0];
    float ty = p[(size_t)HW];
    float tw = p[(size_t)2 * HW];
    float th = p[(size_t)3 * HW];
    float to = p[(size_t)4 * HW];

    // argmax over 80 classes, pairwise-tree per group of 8 (first-occurrence ties)
    const float* pc = p + (size_t)5 * HW;
    float best = -3.402823466e38f;
    int   bcls = 0;
    #pragma unroll
    for (int f = 0; f < 80; f += 8) {
        float v0 = pc[(size_t)(f + 0) * HW];
        float v1 = pc[(size_t)(f + 1) * HW];
        float v2 = pc[(size_t)(f + 2) * HW];
        float v3 = pc[(size_t)(f + 3) * HW];
        float v4 = pc[(size_t)(f + 4) * HW];
        float v5 = pc[(size_t)(f + 5) * HW];
        float v6 = pc[(size_t)(f + 6) * HW];
        float v7 = pc[(size_t)(f + 7) * HW];
        float m01v = (v1 > v0) ? v1 : v0;  int m01i = (v1 > v0) ? f + 1 : f + 0;
        float m23v = (v3 > v2) ? v3 : v2;  int m23i = (v3 > v2) ? f + 3 : f + 2;
        float m45v = (v5 > v4) ? v5 : v4;  int m45i = (v5 > v4) ? f + 5 : f + 4;
        float m67v = (v7 > v6) ? v7 : v6;  int m67i = (v7 > v6) ? f + 7 : f + 6;
        float a03v = (m23v > m01v) ? m23v : m01v;  int a03i = (m23v > m01v) ? m23i : m01i;
        float a47v = (m67v > m45v) ? m67v : m45v;  int a47i = (m67v > m45v) ? m67i : m45i;
        float gv   = (a47v > a03v) ? a47v : a03v;  int gi   = (a47v > a03v) ? a47i : a03i;
        if (gv > best) { best = gv; bcls = gi; }
    }

    float conf = sigm(to);
    float cx   = ((float)x + sigm(tx)) * t;
    float cy   = ((float)y + sigm(ty)) * t;
    float w_   = anc[a * 2 + 0] * expf(tw);
    float h_   = anc[a * 2 + 1] * expf(th);

    int n = n_off + cell * 3 + a;
    float4* bp = (float4*)(g_boxes + ((size_t)b * NBOX + n) * 8);
    bp[0] = make_float4(cx - 0.5f * w_, cy - 0.5f * h_, cx + 0.5f * w_, cy + 0.5f * h_);
    bp[1] = make_float4(conf, (float)bcls, 0.0f, 0.0f);

    unsigned sk = (conf > 0.5f) ? (__float_as_uint(conf) | 0x80000000u) : 0x407FFFFFu;
    g_skey[(size_t)b * NBOX + n] = sk;
    if (conf > 0.5f)
        atomicAdd(&g_hist[b * NBIN + ((sk >> 11) & 0xFFFu)], 1);
}

// ---------------- compact: 8 CTAs per batch -----------------------
// each CTA recomputes the boundary bin from g_hist (cheap), then streams
// its NBOX/8 slice appending survivors to g_sel via global counter.
__global__ void __launch_bounds__(256)
compact_kernel()
{
    __shared__ int sh[NBIN];          // 16 KB
    __shared__ int wsum[8];
    __shared__ int s_B;

    int b     = blockIdx.y;
    int slice = blockIdx.x;           // 0..7
    int tid   = threadIdx.x;
    int lane  = tid & 31;
    int wid   = tid >> 5;

    // load hist coalesced
    const int* gh = g_hist + b * NBIN;
    #pragma unroll
    for (int i = tid; i < NBIN; i += 256) sh[i] = gh[i];
    if (tid == 0) s_B = 0;
    __syncthreads();

    // block-parallel boundary: descending cumulative crosses KTOP
    {
        int hi = NBIN - 1 - 16 * tid;           // bins hi .. hi-15 (desc)
        int hv[16]; int s16 = 0;
        #pragma unroll
        for (int q = 0; q < 16; ++q) { hv[q] = sh[hi - q]; s16 += hv[q]; }
        int pfx = s16;
        #pragma unroll
        for (int d = 1; d < 32; d <<= 1) {
            int v = __shfl_up_sync(0xffffffffu, pfx, d);
            if (lane >= d) pfx += v;
        }
        if (lane == 31) wsum[wid] = pfx;
        __syncthreads();
        if (tid < 8) {
            int v = wsum[tid];
            int p = v;
            #pragma unroll
            for (int d = 1; d < 8; d <<= 1) {
                int u = __shfl_up_sync(0xffu, p, d);
                if (tid >= d) p += u;
            }
            wsum[tid] = p - v;                  // exclusive over warps
        }
        __syncthreads();
        int excl = wsum[wid] + (pfx - s16);
        if (excl < KTOP && excl + s16 >= KTOP) {
            int c = excl;
            #pragma unroll
            for (int q = 0; q < 16; ++q) {
                c += hv[q];
                if (c >= KTOP) { s_B = hi - q; break; }
            }
        }
    }
    __syncthreads();
    int Bbin = s_B;

    // stream slice, append survivors
    const unsigned* gk = g_skey + (size_t)b * NBOX;
    for (int i = slice * 256 + tid; i < NBOX; i += 2048) {
        unsigned sk = gk[i];
        if (sk > 0xBF000000u && (int)((sk >> 11) & 0xFFFu) >= Bbin) {
            int pos = atomicAdd(&g_cnt[b], 1);
            if (pos < 1024)
                g_sel[b * 1024 + pos] =
                    ((unsigned long long)sk << 32) |
                    (unsigned long long)(0xFFFFFFFFu - (unsigned)i);
        }
    }
}

// ---------------- nms: rank-sort + gather + sup + greedy ----------
// dyn smem: sup u32[512*16] @0 (32KB), sel u64[1024] @32768 (8KB),
//           boxes 5*f32[512] @40960 (10KB), cls u8[512] @51200
#define DYN_SMEM 51712

__global__ void __launch_bounds__(1024, 1)
nms_kernel(float* __restrict__ out)
{
    extern __shared__ char dyn[];
    unsigned*           sup = (unsigned*)dyn;
    unsigned long long* sel = (unsigned long long*)(dyn + 32768);
    float* bx1 = (float*)(dyn + 40960);
    float* by1 = bx1 + KTOP;
    float* bx2 = by1 + KTOP;
    float* by2 = bx2 + KTOP;
    float* bar = by2 + KTOP;
    unsigned char* bcl = (unsigned char*)(dyn + 51200);

    __shared__ unsigned validw[16], keepw[16];

    int b    = blockIdx.x;
    int tid  = threadIdx.x;
    int lane = tid & 31;

    int C = g_cnt[b];
    if (C > 1024) C = 1024;

    if (tid < C) sel[tid] = g_sel[b * 1024 + tid];
    if (tid < 16) { validw[tid] = 0u; keepw[tid] = 0u; }
    __syncthreads();

    // ---- rank sort (keys unique -> perfect permutation) + direct gather ----
    if (tid < C) {
        unsigned long long key = sel[tid];
        int rank = 0;
        int j = 0;
        for (; j + 4 <= C; j += 4) {
            rank += (sel[j]     > key);
            rank += (sel[j + 1] > key);
            rank += (sel[j + 2] > key);
            rank += (sel[j + 3] > key);
        }
        for (; j < C; ++j) rank += (sel[j] > key);

        if (rank < KTOP) {
            unsigned idx = 0xFFFFFFFFu - (unsigned)(key & 0xFFFFFFFFull);
            const float4* sp = (const float4*)(g_boxes + ((size_t)b * NBOX + idx) * 8);
            float4 p0 = sp[0], p1 = sp[1];
            bx1[rank] = p0.x; by1[rank] = p0.y; bx2[rank] = p0.z; by2[rank] = p0.w;
            bar[rank] = (p0.z - p0.x) * (p0.w - p0.y);
            bcl[rank] = (unsigned char)(int)p1.y;
            float* dst = out + ((size_t)b * KTOP + rank) * 7;
            dst[0] = p0.x; dst[1] = p0.y; dst[2] = p0.z; dst[3] = p0.w;
            dst[4] = p1.x; dst[5] = p1.y;
            if (p1.x > 0.5f) atomicOr(&validw[rank >> 5], 1u << (rank & 31));
        }
    }
    __syncthreads();

    // ---- forward-only suppress bitmatrix: class-equal gate then IoU ----
    for (int w = tid; w < KTOP * 16; w += 1024) {
        int i  = w >> 4;
        int wj = w & 15;
        int j0 = wj << 5;
        unsigned fwd;
        if (j0 + 31 <= i)      fwd = 0u;
        else if (j0 > i)       fwd = 0xFFFFFFFFu;
        else                   fwd = 0xFFFFFFFFu << (i - j0 + 1);

        unsigned res = 0u;
        if (fwd) {
            unsigned ci4 = (unsigned)bcl[i] * 0x01010101u;
            const unsigned* cp = (const unsigned*)(bcl + j0);
            unsigned bits = 0u;
            #pragma unroll
            for (int qq = 0; qq < 8; ++qq) {
                unsigned eq = __vcmpeq4(cp[qq], ci4);
                unsigned bq = (((eq & 0x01010101u) * 0x01020408u) >> 24) & 0xFu;
                bits |= bq << (qq * 4);
            }
            bits &= fwd;
            if (bits) {
                float x1i = bx1[i], y1i = by1[i], x2i = bx2[i], y2i = by2[i];
                float ai  = bar[i];
                while (bits) {
                    int jj = __ffs(bits) - 1; bits &= bits - 1;
                    int j = j0 + jj;
                    float ix1 = fmaxf(x1i, bx1[j]);
                    float iy1 = fmaxf(y1i, by1[j]);
                    float ix2 = fminf(x2i, bx2[j]);
                    float iy2 = fminf(y2i, by2[j]);
                    float inter = fmaxf(ix2 - ix1, 0.0f) * fmaxf(iy2 - iy1, 0.0f);
                    float iou = inter / (ai + bar[j] - inter + 1e-9f);
                    if (iou > 0.3f) res |= 1u << jj;
                }
            }
        }
        sup[w] = res;
    }
    __syncthreads();

    // ---- chunked greedy scan (warp 0) ----
    if (tid < 32) {
        unsigned cand  = (lane < 16) ? validw[lane] : 0u;
        unsigned keepv = 0u;
        for (int blk = 0; blk < 16; ++blk) {
            unsigned cw = __shfl_sync(0xffffffffu, cand, blk);
            int base = blk << 5;
            unsigned rw = sup[(base + lane) * 16 + blk];   // row base+lane, word blk
            unsigned k32 = 0u;
            #pragma unroll 1
            for (int g = 0; g < 32; g += 8) {
                unsigned s0 = __shfl_sync(0xffffffffu, rw, g + 0);
                unsigned s1 = __shfl_sync(0xffffffffu, rw, g + 1);
                unsigned s2 = __shfl_sync(0xffffffffu, rw, g + 2);
                unsigned s3 = __shfl_sync(0xffffffffu, rw, g + 3);
                unsigned s4 = __shfl_sync(0xffffffffu, rw, g + 4);
                unsigned s5 = __shfl_sync(0xffffffffu, rw, g + 5);
                unsigned s6 = __shfl_sync(0xffffffffu, rw, g + 6);
                unsigned s7 = __shfl_sync(0xffffffffu, rw, g + 7);
                if (cw & (1u << (g + 0))) { k32 |= 1u << (g + 0); cw &= ~s0; }
                if (cw & (1u << (g + 1))) { k32 |= 1u << (g + 1); cw &= ~s1; }
                if (cw & (1u << (g + 2))) { k32 |= 1u << (g + 2); cw &= ~s2; }
                if (cw & (1u << (g + 3))) { k32 |= 1u << (g + 3); cw &= ~s3; }
                if (cw & (1u << (g + 4))) { k32 |= 1u << (g + 4); cw &= ~s4; }
                if (cw & (1u << (g + 5))) { k32 |= 1u << (g + 5); cw &= ~s5; }
                if (cw & (1u << (g + 6))) { k32 |= 1u << (g + 6); cw &= ~s6; }
                if (cw & (1u << (g + 7))) { k32 |= 1u << (g + 7); cw &= ~s7; }
            }
            unsigned t = k32, acc = 0u;
            while (t) {
                int jj = __ffs(t) - 1; t &= t - 1;
                acc |= sup[(base + jj) * 16 + (lane & 15)];
            }
            if (lane > blk && lane < 16) cand &= ~acc;
            if (lane == blk) keepv = k32;
        }
        if (lane < 16) keepw[lane] = keepv;
    }
    __syncthreads();

    if (tid < KTOP) {
        bool k = (keepw[tid >> 5] >> (tid & 31)) & 1u;
        out[((size_t)b * KTOP + tid) * 7 + 6] = k ? 1.0f : 0.0f;
    }
}

// ---------------- launch ------------------------------------------
extern "C" void kernel_launch(void* const* d_in, const int* in_sizes, int n_in,
                              void* d_out, int out_size)
{
    const float* out13 = (const float*)d_in[0];
    const float* out26 = (const float*)d_in[1];
    const float* out52 = (const float*)d_in[2];
    const float* anc13 = (const float*)d_in[3];
    const float* anc26 = (const float*)d_in[4];
    const float* anc52 = (const float*)d_in[5];
    float* out = (float*)d_out;

    const int TPB = 256;
    zero_kernel<<<(BATCH * NBIN + TPB - 1) / TPB, TPB>>>();
    decode_all_kernel<<<(TTOT + TPB - 1) / TPB, TPB>>>(out13, out26, out52,
                                                       anc13, anc26, anc52);
    dim3 cg(8, BATCH);
    compact_kernel<<<cg, TPB>>>();

    static bool attr_set = false;
    if (!attr_set) {
        cudaFuncSetAttribute(nms_kernel,
                             cudaFuncAttributeMaxDynamicSharedMemorySize, DYN_SMEM);
        attr_set = true;
    }
    nms_kernel<<<BATCH, 1024, DYN_SMEM>>>(out);
}

// round 6
// speedup vs baseline: 1.2938x; 1.2938x over previous
#include <cuda_runtime.h>
#include <stdint.h>
#include <math.h>

#define BATCH 32
#define NBOX  10647          // 507 + 2028 + 8112
#define KTOP  512
#define NBIN  4096
#define T13   (BATCH * 3 * 169)
#define T26   (BATCH * 3 * 676)
#define T52   (BATCH * 3 * 2704)
#define TTOT  (T13 + T26 + T52)

// ---------------- scratch (no allocation allowed) ----------------
__device__ float              g_boxes[BATCH * NBOX * 8];  // x1,y1,x2,y2,conf,cls,pad,pad
__device__ unsigned           g_skey [BATCH * NBOX];      // mono32(score)
__device__ int                g_hist [BATCH * NBIN];
__device__ int                g_cnt  [BATCH];
__device__ unsigned long long g_sel  [BATCH * 1024];
__device__ unsigned           g_sup  [BATCH * KTOP * 16]; // suppress bitmatrix
__device__ unsigned           g_valid[BATCH * 16];

__device__ __forceinline__ float sigm(float x) {
    return 1.0f / (1.0f + expf(-x));
}

// ---------------- zero scratch ------------------------------------
__global__ void zero_kernel()
{
    int i = blockIdx.x * blockDim.x + threadIdx.x;
    if (i < BATCH * NBIN) g_hist[i] = 0;
    if (i < BATCH)        g_cnt[i]  = 0;
    if (i < BATCH * 16)   g_valid[i] = 0u;
}

// ---------------- fused decode + histogram ------------------------
__global__ void __launch_bounds__(256)
decode_all_kernel(const float* __restrict__ o13, const float* __restrict__ o26,
                  const float* __restrict__ o52, const float* __restrict__ a13,
                  const float* __restrict__ a26, const float* __restrict__ a52)
{
    int gid = blockIdx.x * blockDim.x + threadIdx.x;
    if (gid >= TTOT) return;

    const float* src; const float* anc;
    int HW, W, n_off, r;
    float t;
    if (gid < T13)            { r = gid;             src = o13; anc = a13; HW = 169;  W = 13; n_off = 0;    t = 32.0f; }
    else if (gid < T13 + T26) { r = gid - T13;       src = o26; anc = a26; HW = 676;  W = 26; n_off = 507;  t = 16.0f; }
    else                      { r = gid - T13 - T26; src = o52; anc = a52; HW = 2704; W = 52; n_off = 2535; t = 8.0f;  }

    int b    = r / (3 * HW);
    int q    = r - b * 3 * HW;
    int a    = q / HW;
    int cell = q - a * HW;
    int y    = cell / W;
    int x    = cell - y * W;

    const float* p = src + ((size_t)b * 255 + (size_t)a * 85) * HW + cell;

    float tx = p[0];
    float ty = p[(size_t)HW];
    float tw = p[(size_t)2 * HW];
    float th = p[(size_t)3 * HW];
    float to = p[(size_t)4 * HW];

    // argmax over 80 classes, pairwise-tree per group of 8 (first-occurrence ties)
    const float* pc = p + (size_t)5 * HW;
    float best = -3.402823466e38f;
    int   bcls = 0;
    #pragma unroll
    for (int f = 0; f < 80; f += 8) {
        float v0 = pc[(size_t)(f + 0) * HW];
        float v1 = pc[(size_t)(f + 1) * HW];
        float v2 = pc[(size_t)(f + 2) * HW];
        float v3 = pc[(size_t)(f + 3) * HW];
        float v4 = pc[(size_t)(f + 4) * HW];
        float v5 = pc[(size_t)(f + 5) * HW];
        float v6 = pc[(size_t)(f + 6) * HW];
        float v7 = pc[(size_t)(f + 7) * HW];
        float m01v = (v1 > v0) ? v1 : v0;  int m01i = (v1 > v0) ? f + 1 : f + 0;
        float m23v = (v3 > v2) ? v3 : v2;  int m23i = (v3 > v2) ? f + 3 : f + 2;
        float m45v = (v5 > v4) ? v5 : v4;  int m45i = (v5 > v4) ? f + 5 : f + 4;
        float m67v = (v7 > v6) ? v7 : v6;  int m67i = (v7 > v6) ? f + 7 : f + 6;
        float a03v = (m23v > m01v) ? m23v : m01v;  int a03i = (m23v > m01v) ? m23i : m01i;
        float a47v = (m67v > m45v) ? m67v : m45v;  int a47i = (m67v > m45v) ? m67i : m45i;
        float gv   = (a47v > a03v) ? a47v : a03v;  int gi   = (a47v > a03v) ? a47i : a03i;
        if (gv > best) { best = gv; bcls = gi; }
    }

    float conf = sigm(to);
    float cx   = ((float)x + sigm(tx)) * t;
    float cy   = ((float)y + sigm(ty)) * t;
    float w_   = anc[a * 2 + 0] * expf(tw);
    float h_   = anc[a * 2 + 1] * expf(th);

    int n = n_off + cell * 3 + a;
    float4* bp = (float4*)(g_boxes + ((size_t)b * NBOX + n) * 8);
    bp[0] = make_float4(cx - 0.5f * w_, cy - 0.5f * h_, cx + 0.5f * w_, cy + 0.5f * h_);
    bp[1] = make_float4(conf, (float)bcls, 0.0f, 0.0f);

    unsigned sk = (conf > 0.5f) ? (__float_as_uint(conf) | 0x80000000u) : 0x407FFFFFu;
    g_skey[(size_t)b * NBOX + n] = sk;
    if (conf > 0.5f)
        atomicAdd(&g_hist[b * NBIN + ((sk >> 11) & 0xFFFu)], 1);
}

// ---------------- compact: 8 CTAs per batch -----------------------
__global__ void __launch_bounds__(256)
compact_kernel()
{
    __shared__ int sh[NBIN];          // 16 KB
    __shared__ int wsum[8];
    __shared__ int s_B;

    int b     = blockIdx.y;
    int slice = blockIdx.x;           // 0..7
    int tid   = threadIdx.x;
    int lane  = tid & 31;
    int wid   = tid >> 5;

    const int* gh = g_hist + b * NBIN;
    #pragma unroll
    for (int i = tid; i < NBIN; i += 256) sh[i] = gh[i];
    if (tid == 0) s_B = 0;
    __syncthreads();

    // block-parallel boundary: descending cumulative crosses KTOP
    {
        int hi = NBIN - 1 - 16 * tid;           // bins hi .. hi-15 (desc)
        int hv[16]; int s16 = 0;
        #pragma unroll
        for (int q = 0; q < 16; ++q) { hv[q] = sh[hi - q]; s16 += hv[q]; }
        int pfx = s16;
        #pragma unroll
        for (int d = 1; d < 32; d <<= 1) {
            int v = __shfl_up_sync(0xffffffffu, pfx, d);
            if (lane >= d) pfx += v;
        }
        if (lane == 31) wsum[wid] = pfx;
        __syncthreads();
        if (tid < 8) {
            int v = wsum[tid];
            int p = v;
            #pragma unroll
            for (int d = 1; d < 8; d <<= 1) {
                int u = __shfl_up_sync(0xffu, p, d);
                if (tid >= d) p += u;
            }
            wsum[tid] = p - v;
        }
        __syncthreads();
        int excl = wsum[wid] + (pfx - s16);
        if (excl < KTOP && excl + s16 >= KTOP) {
            int c = excl;
            #pragma unroll
            for (int q = 0; q < 16; ++q) {
                c += hv[q];
                if (c >= KTOP) { s_B = hi - q; break; }
            }
        }
    }
    __syncthreads();
    int Bbin = s_B;

    const unsigned* gk = g_skey + (size_t)b * NBOX;
    for (int i = slice * 256 + tid; i < NBOX; i += 2048) {
        unsigned sk = gk[i];
        if (sk > 0xBF000000u && (int)((sk >> 11) & 0xFFFu) >= Bbin) {
            int pos = atomicAdd(&g_cnt[b], 1);
            if (pos < 1024)
                g_sel[b * 1024 + pos] =
                    ((unsigned long long)sk << 32) |
                    (unsigned long long)(0xFFFFFFFFu - (unsigned)i);
        }
    }
}

// ---------------- rank-sort + gather -> out rows ------------------
__global__ void __launch_bounds__(1024, 1)
rank_kernel(float* __restrict__ out)
{
    __shared__ unsigned long long sel[1024];
    __shared__ unsigned validw[16];

    int b   = blockIdx.x;
    int tid = threadIdx.x;

    int C = g_cnt[b];
    if (C > 1024) C = 1024;

    if (tid < C) sel[tid] = g_sel[b * 1024 + tid];
    if (tid < 16) validw[tid] = 0u;
    __syncthreads();

    if (tid < C) {
        unsigned long long key = sel[tid];
        int rank = 0;
        int j = 0;
        for (; j + 8 <= C; j += 8) {
            rank += (sel[j]     > key) + (sel[j + 1] > key)
                  + (sel[j + 2] > key) + (sel[j + 3] > key)
                  + (sel[j + 4] > key) + (sel[j + 5] > key)
                  + (sel[j + 6] > key) + (sel[j + 7] > key);
        }
        for (; j < C; ++j) rank += (sel[j] > key);

        if (rank < KTOP) {
            unsigned idx = 0xFFFFFFFFu - (unsigned)(key & 0xFFFFFFFFull);
            const float4* sp = (const float4*)(g_boxes + ((size_t)b * NBOX + idx) * 8);
            float4 p0 = sp[0], p1 = sp[1];
            float* dst = out + ((size_t)b * KTOP + rank) * 7;
            dst[0] = p0.x; dst[1] = p0.y; dst[2] = p0.z; dst[3] = p0.w;
            dst[4] = p1.x; dst[5] = p1.y;
            if (p1.x > 0.5f) atomicOr(&validw[rank >> 5], 1u << (rank & 31));
        }
    }
    __syncthreads();
    if (tid < 16) g_valid[b * 16 + tid] = validw[tid];
}

// ---------------- sup bitmatrix: 8 CTAs per batch -----------------
__global__ void __launch_bounds__(256)
sup_kernel(const float* __restrict__ out)
{
    __shared__ float sx1[KTOP], sy1[KTOP], sx2[KTOP], sy2[KTOP], sar[KTOP];
    __shared__ unsigned char scl[KTOP];

    int b   = blockIdx.y;
    int tid = threadIdx.x;
    const float* base = out + (size_t)b * KTOP * 7;

    for (int i = tid; i < KTOP; i += 256) {
        const float* r = base + (size_t)i * 7;
        float x1 = r[0], y1 = r[1], x2 = r[2], y2 = r[3];
        sx1[i] = x1; sy1[i] = y1; sx2[i] = x2; sy2[i] = y2;
        sar[i] = (x2 - x1) * (y2 - y1);
        scl[i] = (unsigned char)(int)r[5];
    }
    __syncthreads();

    // this CTA covers 64 rows = 1024 words; 4 words per thread
    int w0 = blockIdx.x * 1024;
    #pragma unroll
    for (int it = 0; it < 4; ++it) {
        int w  = w0 + it * 256 + tid;
        int i  = w >> 4;
        int wj = w & 15;
        int j0 = wj << 5;
        unsigned fwd;
        if (j0 + 31 <= i)      fwd = 0u;
        else if (j0 > i)       fwd = 0xFFFFFFFFu;
        else                   fwd = 0xFFFFFFFFu << (i - j0 + 1);

        unsigned res = 0u;
        if (fwd) {
            unsigned ci4 = (unsigned)scl[i] * 0x01010101u;
            const unsigned* cp = (const unsigned*)(scl + j0);
            unsigned bits = 0u;
            #pragma unroll
            for (int qq = 0; qq < 8; ++qq) {
                unsigned eq = __vcmpeq4(cp[qq], ci4);
                unsigned bq = (((eq & 0x01010101u) * 0x01020408u) >> 24) & 0xFu;
                bits |= bq << (qq * 4);
            }
            bits &= fwd;
            if (bits) {
                float x1i = sx1[i], y1i = sy1[i], x2i = sx2[i], y2i = sy2[i];
                float ai  = sar[i];
                while (bits) {
                    int jj = __ffs(bits) - 1; bits &= bits - 1;
                    int j = j0 + jj;
                    float ix1 = fmaxf(x1i, sx1[j]);
                    float iy1 = fmaxf(y1i, sy1[j]);
                    float ix2 = fminf(x2i, sx2[j]);
                    float iy2 = fminf(y2i, sy2[j]);
                    float inter = fmaxf(ix2 - ix1, 0.0f) * fmaxf(iy2 - iy1, 0.0f);
                    float iou = inter / (ai + sar[j] - inter + 1e-9f);
                    if (iou > 0.3f) res |= 1u << jj;
                }
            }
        }
        g_sup[b * (KTOP * 16) + w] = res;
    }
}

// ---------------- greedy: one CTA per batch -----------------------
__global__ void __launch_bounds__(1024, 1)
greedy_kernel(float* __restrict__ out)
{
    __shared__ unsigned sup[KTOP * 16];     // 32 KB
    __shared__ unsigned validw[16], keepw[16];

    int b    = blockIdx.x;
    int tid  = threadIdx.x;
    int lane = tid & 31;

    const unsigned* gs = g_sup + b * (KTOP * 16);
    #pragma unroll
    for (int i = tid; i < KTOP * 16; i += 1024) sup[i] = gs[i];
    if (tid < 16) validw[tid] = g_valid[b * 16 + tid];
    __syncthreads();

    if (tid < 32) {
        unsigned cand  = (lane < 16) ? validw[lane] : 0u;
        unsigned keepv = 0u;
        for (int blk = 0; blk < 16; ++blk) {
            unsigned cw = __shfl_sync(0xffffffffu, cand, blk);
            int base = blk << 5;
            unsigned rw = sup[(base + lane) * 16 + blk];   // row base+lane, word blk
            unsigned k32 = 0u;
            #pragma unroll 1
            for (int g = 0; g < 32; g += 8) {
                unsigned s0 = __shfl_sync(0xffffffffu, rw, g + 0);
                unsigned s1 = __shfl_sync(0xffffffffu, rw, g + 1);
                unsigned s2 = __shfl_sync(0xffffffffu, rw, g + 2);
                unsigned s3 = __shfl_sync(0xffffffffu, rw, g + 3);
                unsigned s4 = __shfl_sync(0xffffffffu, rw, g + 4);
                unsigned s5 = __shfl_sync(0xffffffffu, rw, g + 5);
                unsigned s6 = __shfl_sync(0xffffffffu, rw, g + 6);
                unsigned s7 = __shfl_sync(0xffffffffu, rw, g + 7);
                if (cw & (1u << (g + 0))) { k32 |= 1u << (g + 0); cw &= ~s0; }
                if (cw & (1u << (g + 1))) { k32 |= 1u << (g + 1); cw &= ~s1; }
                if (cw & (1u << (g + 2))) { k32 |= 1u << (g + 2); cw &= ~s2; }
                if (cw & (1u << (g + 3))) { k32 |= 1u << (g + 3); cw &= ~s3; }
                if (cw & (1u << (g + 4))) { k32 |= 1u << (g + 4); cw &= ~s4; }
                if (cw & (1u << (g + 5))) { k32 |= 1u << (g + 5); cw &= ~s5; }
                if (cw & (1u << (g + 6))) { k32 |= 1u << (g + 6); cw &= ~s6; }
                if (cw & (1u << (g + 7))) { k32 |= 1u << (g + 7); cw &= ~s7; }
            }
            // dense apply: 32 independent masked loads (no serial ffs chain)
            unsigned acc = 0u;
            if (lane < 16) {
                #pragma unroll
                for (int j = 0; j < 32; ++j) {
                    unsigned m = 0u - ((k32 >> j) & 1u);
                    acc |= sup[(base + j) * 16 + lane] & m;
                }
            }
            if (lane > blk && lane < 16) cand &= ~acc;
            if (lane == blk) keepv = k32;
        }
        if (lane < 16) keepw[lane] = keepv;
    }
    __syncthreads();

    if (tid < KTOP) {
        bool k = (keepw[tid >> 5] >> (tid & 31)) & 1u;
        out[((size_t)b * KTOP + tid) * 7 + 6] = k ? 1.0f : 0.0f;
    }
}

// ---------------- launch ------------------------------------------
extern "C" void kernel_launch(void* const* d_in, const int* in_sizes, int n_in,
                              void* d_out, int out_size)
{
    const float* out13 = (const float*)d_in[0];
    const float* out26 = (const float*)d_in[1];
    const float* out52 = (const float*)d_in[2];
    const float* anc13 = (const float*)d_in[3];
    const float* anc26 = (const float*)d_in[4];
    const float* anc52 = (const float*)d_in[5];
    float* out = (float*)d_out;

    const int TPB = 256;
    zero_kernel<<<(BATCH * NBIN + TPB - 1) / TPB, TPB>>>();
    decode_all_kernel<<<(TTOT + TPB - 1) / TPB, TPB>>>(out13, out26, out52,
                                                       anc13, anc26, anc52);
    dim3 cg(8, BATCH);
    compact_kernel<<<cg, TPB>>>();
    rank_kernel<<<BATCH, 1024>>>(out);
    dim3 sg(8, BATCH);
    sup_kernel<<<sg, TPB>>>(out);
    greedy_kernel<<<BATCH, 1024>>>(out);
}

// round 7
// speedup vs baseline: 1.5017x; 1.1608x over previous
#include <cuda_runtime.h>
#include <stdint.h>
#include <math.h>

#define BATCH 32
#define NBOX  10647          // 507 + 2028 + 8112
#define KTOP  512
#define NBIN  4096
#define T13   (BATCH * 3 * 169)
#define T26   (BATCH * 3 * 676)
#define T52   (BATCH * 3 * 2704)
#define TTOT  (T13 + T26 + T52)

// ---------------- scratch (no allocation allowed) ----------------
__device__ float    g_boxes[BATCH * NBOX * 8];  // x1,y1,x2,y2,conf,cls,pad,pad
__device__ unsigned g_skey [BATCH * NBOX];      // mono32(score)
__device__ unsigned g_valid[BATCH * 16];

__device__ __forceinline__ float sigm(float x) {
    return 1.0f / (1.0f + expf(-x));
}

// ---------------- decode: all 3 scales, one launch ----------------
__global__ void __launch_bounds__(256)
decode_all_kernel(const float* __restrict__ o13, const float* __restrict__ o26,
                  const float* __restrict__ o52, const float* __restrict__ a13,
                  const float* __restrict__ a26, const float* __restrict__ a52)
{
    int gid = blockIdx.x * blockDim.x + threadIdx.x;
    if (gid >= TTOT) return;

    const float* src; const float* anc;
    int HW, W, n_off, r;
    float t;
    if (gid < T13)            { r = gid;             src = o13; anc = a13; HW = 169;  W = 13; n_off = 0;    t = 32.0f; }
    else if (gid < T13 + T26) { r = gid - T13;       src = o26; anc = a26; HW = 676;  W = 26; n_off = 507;  t = 16.0f; }
    else                      { r = gid - T13 - T26; src = o52; anc = a52; HW = 2704; W = 52; n_off = 2535; t = 8.0f;  }

    int b    = r / (3 * HW);
    int q    = r - b * 3 * HW;
    int a    = q / HW;
    int cell = q - a * HW;
    int y    = cell / W;
    int x    = cell - y * W;

    const float* p = src + ((size_t)b * 255 + (size_t)a * 85) * HW + cell;

    float tx = p[0];
    float ty = p[(size_t)HW];
    float tw = p[(size_t)2 * HW];
    float th = p[(size_t)3 * HW];
    float to = p[(size_t)4 * HW];

    // argmax over 80 classes, pairwise-tree per group of 8 (first-occurrence ties)
    const float* pc = p + (size_t)5 * HW;
    float best = -3.402823466e38f;
    int   bcls = 0;
    #pragma unroll
    for (int f = 0; f < 80; f += 8) {
        float v0 = pc[(size_t)(f + 0) * HW];
        float v1 = pc[(size_t)(f + 1) * HW];
        float v2 = pc[(size_t)(f + 2) * HW];
        float v3 = pc[(size_t)(f + 3) * HW];
        float v4 = pc[(size_t)(f + 4) * HW];
        float v5 = pc[(size_t)(f + 5) * HW];
        float v6 = pc[(size_t)(f + 6) * HW];
        float v7 = pc[(size_t)(f + 7) * HW];
        float m01v = (v1 > v0) ? v1 : v0;  int m01i = (v1 > v0) ? f + 1 : f + 0;
        float m23v = (v3 > v2) ? v3 : v2;  int m23i = (v3 > v2) ? f + 3 : f + 2;
        float m45v = (v5 > v4) ? v5 : v4;  int m45i = (v5 > v4) ? f + 5 : f + 4;
        float m67v = (v7 > v6) ? v7 : v6;  int m67i = (v7 > v6) ? f + 7 : f + 6;
        float a03v = (m23v > m01v) ? m23v : m01v;  int a03i = (m23v > m01v) ? m23i : m01i;
        float a47v = (m67v > m45v) ? m67v : m45v;  int a47i = (m67v > m45v) ? m67i : m45i;
        float gv   = (a47v > a03v) ? a47v : a03v;  int gi   = (a47v > a03v) ? a47i : a03i;
        if (gv > best) { best = gv; bcls = gi; }
    }

    float conf = sigm(to);
    float cx   = ((float)x + sigm(tx)) * t;
    float cy   = ((float)y + sigm(ty)) * t;
    float w_   = anc[a * 2 + 0] * expf(tw);
    float h_   = anc[a * 2 + 1] * expf(th);

    int n = n_off + cell * 3 + a;
    float4* bp = (float4*)(g_boxes + ((size_t)b * NBOX + n) * 8);
    bp[0] = make_float4(cx - 0.5f * w_, cy - 0.5f * h_, cx + 0.5f * w_, cy + 0.5f * h_);
    bp[1] = make_float4(conf, (float)bcls, 0.0f, 0.0f);
    g_skey[(size_t)b * NBOX + n] =
        (conf > 0.5f) ? (__float_as_uint(conf) | 0x80000000u) : 0x407FFFFFu;
}

// ======== K2: per-batch hist + select + two-level rank + gather ========
// dyn smem: hist int[4096] @0, cum int[4096] @16384, cumw int[4096] @32768,
//           sel u64[1024] @49152  -> 57344 B
#define K2_SMEM 57344

__global__ void __launch_bounds__(1024, 1)
select_rank_kernel(float* __restrict__ out)
{
    extern __shared__ char dyn[];
    int*                hist = (int*)dyn;
    int*                cum  = (int*)(dyn + 16384);
    int*                cumw = (int*)(dyn + 32768);
    unsigned long long* sel  = (unsigned long long*)(dyn + 49152);

    __shared__ int      wsum[32];
    __shared__ int      s_B;
    __shared__ unsigned validw[16];

    int b    = blockIdx.x;
    int tid  = threadIdx.x;
    int lane = tid & 31;
    int wid  = tid >> 5;
    const unsigned* gk = g_skey + (size_t)b * NBOX;

    #pragma unroll
    for (int i = tid; i < NBIN; i += 1024) hist[i] = 0;
    if (tid == 0) s_B = 0;
    if (tid < 16) validw[tid] = 0u;
    __syncthreads();

    // ---- histogram over mantissa bits [11,23) of passing scores ----
    for (int i = tid; i < NBOX; i += 1024) {
        unsigned sk = gk[i];
        if (sk > 0xBF000000u)                       // conf > 0.5 strictly
            atomicAdd(&hist[(sk >> 11) & 0xFFFu], 1);
    }
    __syncthreads();

    // ---- descending exclusive cumsum + boundary bin ----
    {
        int hi = NBIN - 1 - 4 * tid;                // thread covers hi..hi-3 (desc)
        int h0 = hist[hi], h1 = hist[hi - 1], h2 = hist[hi - 2], h3 = hist[hi - 3];
        int s4 = h0 + h1 + h2 + h3;
        int pfx = s4;
        #pragma unroll
        for (int d = 1; d < 32; d <<= 1) {
            int v = __shfl_up_sync(0xffffffffu, pfx, d);
            if (lane >= d) pfx += v;
        }
        if (lane == 31) wsum[wid] = pfx;
        __syncthreads();
        if (tid < 32) {
            int v = wsum[lane];
            int p = v;
            #pragma unroll
            for (int d = 1; d < 32; d <<= 1) {
                int u = __shfl_up_sync(0xffffffffu, p, d);
                if (lane >= d) p += u;
            }
            wsum[lane] = p - v;                     // exclusive over warps
        }
        __syncthreads();
        int excl = wsum[wid] + (pfx - s4);          // # keys in bins > hi
        cum[hi]     = excl;              cumw[hi]     = excl;
        cum[hi - 1] = excl + h0;         cumw[hi - 1] = excl + h0;
        cum[hi - 2] = excl + h0 + h1;    cumw[hi - 2] = excl + h0 + h1;
        cum[hi - 3] = excl + h0 + h1 + h2; cumw[hi - 3] = excl + h0 + h1 + h2;
        if (excl < KTOP && excl + s4 >= KTOP) {
            int c = excl;
            if      (c + h0 >= KTOP)           s_B = hi;
            else if (c + h0 + h1 >= KTOP)      s_B = hi - 1;
            else if (c + h0 + h1 + h2 >= KTOP) s_B = hi - 2;
            else                               s_B = hi - 3;
        }
    }
    __syncthreads();
    int Bbin = s_B;

    // ---- scatter passing keys to bin-sorted slots ----
    for (int i = tid; i < NBOX; i += 1024) {
        unsigned sk = gk[i];
        if (sk > 0xBF000000u) {
            int bin = (sk >> 11) & 0xFFFu;
            if (bin >= Bbin) {
                int slot = atomicAdd(&cumw[bin], 1);
                if (slot < 1024)
                    sel[slot] = ((unsigned long long)sk << 32) |
                                (unsigned long long)(0xFFFFFFFFu - (unsigned)i);
            }
        }
    }
    __syncthreads();

    // ---- exact rank = base + intra-bin compares (avg ~1.3) + gather ----
    int C = cum[Bbin] + hist[Bbin];
    if (C > 1024) C = 1024;
    if (tid < C) {
        unsigned long long key = sel[tid];
        int bin  = (int)((key >> 43) & 0xFFFull);
        int base = cum[bin];
        int cnt  = hist[bin];
        int end  = base + cnt; if (end > 1024) end = 1024;
        int rank = base;
        for (int j = base; j < end; ++j) rank += (sel[j] > key);
        if (rank < KTOP) {
            unsigned idx = 0xFFFFFFFFu - (unsigned)(key & 0xFFFFFFFFull);
            const float4* sp = (const float4*)(g_boxes + ((size_t)b * NBOX + idx) * 8);
            float4 p0 = sp[0], p1 = sp[1];
            float* dst = out + ((size_t)b * KTOP + rank) * 7;
            dst[0] = p0.x; dst[1] = p0.y; dst[2] = p0.z; dst[3] = p0.w;
            dst[4] = p1.x; dst[5] = p1.y;
            if (p1.x > 0.5f) atomicOr(&validw[rank >> 5], 1u << (rank & 31));
        }
    }
    __syncthreads();
    if (tid < 16) g_valid[b * 16 + tid] = validw[tid];
}

// ======== K3: fused sup bitmatrix + greedy, one CTA per batch ========
__global__ void __launch_bounds__(1024, 1)
nms_kernel(float* __restrict__ out)
{
    __shared__ float sx1[KTOP], sy1[KTOP], sx2[KTOP], sy2[KTOP], sar[KTOP];
    __shared__ unsigned char scl[KTOP];
    __shared__ unsigned sup[KTOP * 16];     // 32 KB
    __shared__ unsigned validw[16], keepw[16];

    int b    = blockIdx.x;
    int tid  = threadIdx.x;
    int lane = tid & 31;
    const float* base_row = out + (size_t)b * KTOP * 7;

    if (tid < KTOP) {
        const float* r = base_row + (size_t)tid * 7;
        float x1 = r[0], y1 = r[1], x2 = r[2], y2 = r[3];
        sx1[tid] = x1; sy1[tid] = y1; sx2[tid] = x2; sy2[tid] = y2;
        sar[tid] = (x2 - x1) * (y2 - y1);
        scl[tid] = (unsigned char)(int)r[5];
    }
    if (tid < 16) { validw[tid] = g_valid[b * 16 + tid]; keepw[tid] = 0u; }
    __syncthreads();

    // ---- forward-only suppress bitmatrix (8 words/thread) ----
    #pragma unroll
    for (int w = tid; w < KTOP * 16; w += 1024) {
        int i  = w >> 4;
        int wj = w & 15;
        int j0 = wj << 5;
        unsigned fwd;
        if (j0 + 31 <= i)      fwd = 0u;
        else if (j0 > i)       fwd = 0xFFFFFFFFu;
        else                   fwd = 0xFFFFFFFFu << (i - j0 + 1);

        unsigned res = 0u;
        if (fwd) {
            unsigned ci4 = (unsigned)scl[i] * 0x01010101u;
            const unsigned* cp = (const unsigned*)(scl + j0);
            unsigned bits = 0u;
            #pragma unroll
            for (int qq = 0; qq < 8; ++qq) {
                unsigned eq = __vcmpeq4(cp[qq], ci4);
                unsigned bq = (((eq & 0x01010101u) * 0x01020408u) >> 24) & 0xFu;
                bits |= bq << (qq * 4);
            }
            bits &= fwd;
            if (bits) {
                float x1i = sx1[i], y1i = sy1[i], x2i = sx2[i], y2i = sy2[i];
                float ai  = sar[i];
                while (bits) {
                    int jj = __ffs(bits) - 1; bits &= bits - 1;
                    int j = j0 + jj;
                    float ix1 = fmaxf(x1i, sx1[j]);
                    float iy1 = fmaxf(y1i, sy1[j]);
                    float ix2 = fminf(x2i, sx2[j]);
                    float iy2 = fminf(y2i, sy2[j]);
                    float inter = fmaxf(ix2 - ix1, 0.0f) * fmaxf(iy2 - iy1, 0.0f);
                    float iou = inter / (ai + sar[j] - inter + 1e-9f);
                    if (iou > 0.3f) res |= 1u << jj;
                }
            }
        }
        sup[w] = res;
    }
    __syncthreads();

    // ---- chunked greedy scan (warp 0) ----
    if (tid < 32) {
        unsigned cand  = (lane < 16) ? validw[lane] : 0u;
        unsigned keepv = 0u;
        for (int blk = 0; blk < 16; ++blk) {
            unsigned cw = __shfl_sync(0xffffffffu, cand, blk);
            int base = blk << 5;
            unsigned rw = sup[(base + lane) * 16 + blk];   // row base+lane, word blk
            unsigned k32 = 0u;
            #pragma unroll 1
            for (int g = 0; g < 32; g += 8) {
                unsigned s0 = __shfl_sync(0xffffffffu, rw, g + 0);
                unsigned s1 = __shfl_sync(0xffffffffu, rw, g + 1);
                unsigned s2 = __shfl_sync(0xffffffffu, rw, g + 2);
                unsigned s3 = __shfl_sync(0xffffffffu, rw, g + 3);
                unsigned s4 = __shfl_sync(0xffffffffu, rw, g + 4);
                unsigned s5 = __shfl_sync(0xffffffffu, rw, g + 5);
                unsigned s6 = __shfl_sync(0xffffffffu, rw, g + 6);
                unsigned s7 = __shfl_sync(0xffffffffu, rw, g + 7);
                if (cw & (1u << (g + 0))) { k32 |= 1u << (g + 0); cw &= ~s0; }
                if (cw & (1u << (g + 1))) { k32 |= 1u << (g + 1); cw &= ~s1; }
                if (cw & (1u << (g + 2))) { k32 |= 1u << (g + 2); cw &= ~s2; }
                if (cw & (1u << (g + 3))) { k32 |= 1u << (g + 3); cw &= ~s3; }
                if (cw & (1u << (g + 4))) { k32 |= 1u << (g + 4); cw &= ~s4; }
                if (cw & (1u << (g + 5))) { k32 |= 1u << (g + 5); cw &= ~s5; }
                if (cw & (1u << (g + 6))) { k32 |= 1u << (g + 6); cw &= ~s6; }
                if (cw & (1u << (g + 7))) { k32 |= 1u << (g + 7); cw &= ~s7; }
            }
            // dense apply: 32 independent masked loads
            unsigned acc = 0u;
            if (lane < 16) {
                #pragma unroll
                for (int j = 0; j < 32; ++j) {
                    unsigned m = 0u - ((k32 >> j) & 1u);
                    acc |= sup[(base + j) * 16 + lane] & m;
                }
            }
            if (lane > blk && lane < 16) cand &= ~acc;
            if (lane == blk) keepv = k32;
        }
        if (lane < 16) keepw[lane] = keepv;
    }
    __syncthreads();

    if (tid < KTOP) {
        bool k = (keepw[tid >> 5] >> (tid & 31)) & 1u;
        out[((size_t)b * KTOP + tid) * 7 + 6] = k ? 1.0f : 0.0f;
    }
}

// ---------------- launch ------------------------------------------
extern "C" void kernel_launch(void* const* d_in, const int* in_sizes, int n_in,
                              void* d_out, int out_size)
{
    const float* out13 = (const float*)d_in[0];
    const float* out26 = (const float*)d_in[1];
    const float* out52 = (const float*)d_in[2];
    const float* anc13 = (const float*)d_in[3];
    const float* anc26 = (const float*)d_in[4];
    const float* anc52 = (const float*)d_in[5];
    float* out = (float*)d_out;

    const int TPB = 256;
    decode_all_kernel<<<(TTOT + TPB - 1) / TPB, TPB>>>(out13, out26, out52,
                                                       anc13, anc26, anc52);

    static bool attr_set = false;
    if (!attr_set) {
        cudaFuncSetAttribute(select_rank_kernel,
                             cudaFuncAttributeMaxDynamicSharedMemorySize, K2_SMEM);
        attr_set = true;
    }
    select_rank_kernel<<<BATCH, 1024, K2_SMEM>>>(out);
    nms_kernel<<<BATCH, 1024>>>(out);
}